// round 16
// baseline (speedup 1.0000x reference)
#include <cuda_runtime.h>
#include <cuda_pipeline.h>

#define FULLMASK 0xffffffffu

constexpr int Nn = 8;
constexpr int Cc = 128;
constexpr int Hh = 160;
constexpr int Ww = 160;
constexpr int HW  = Hh * Ww;
constexpr int WC  = Ww * Cc;
constexpr int HWC = Hh * WC;             // per-image NHWC stride
constexpr int TOT = Nn * HWC;

// Single in-place NHWC scratch buffer.
__device__ float g_buf[TOT];

__device__ __forceinline__ float4 ld4(const float* p)  { return *(const float4*)p; }

__device__ __forceinline__ float4 relu4(float a, float b, float c, float d) {
    return make_float4(fmaxf(a, 0.f), fmaxf(b, 0.f), fmaxf(c, 0.f), fmaxf(d, 0.f));
}

// One scan step: carry d0..d3 (pre-relu state, 4 consecutive channels/lane),
// 9-tap conv along C via lane shuffles, zero-padded at C boundaries.
// d_new = relu(conv(d) + b) + x. Split accumulators shorten the FMA chain.
__device__ __forceinline__ void scan_step(float& d0, float& d1, float& d2, float& d3,
                                          float x0, float x1, float x2, float x3,
                                          const float wk[9], float b, int lane)
{
    float v[12];
    v[4] = d0; v[5] = d1; v[6] = d2; v[7] = d3;
    v[0]  = __shfl_up_sync(FULLMASK, d0, 1);
    v[1]  = __shfl_up_sync(FULLMASK, d1, 1);
    v[2]  = __shfl_up_sync(FULLMASK, d2, 1);
    v[3]  = __shfl_up_sync(FULLMASK, d3, 1);
    v[8]  = __shfl_down_sync(FULLMASK, d0, 1);
    v[9]  = __shfl_down_sync(FULLMASK, d1, 1);
    v[10] = __shfl_down_sync(FULLMASK, d2, 1);
    v[11] = __shfl_down_sync(FULLMASK, d3, 1);
    if (lane == 0)  { v[0] = 0.f; v[1] = 0.f; v[2]  = 0.f; v[3]  = 0.f; }
    if (lane == 31) { v[8] = 0.f; v[9] = 0.f; v[10] = 0.f; v[11] = 0.f; }
    float a0 = b, a1 = b, a2 = b, a3 = b;
    float e0 = 0.f, e1 = 0.f, e2 = 0.f, e3 = 0.f;
#pragma unroll
    for (int k = 0; k < 5; k++) {
        a0 = fmaf(wk[k], v[k + 0], a0);
        a1 = fmaf(wk[k], v[k + 1], a1);
        a2 = fmaf(wk[k], v[k + 2], a2);
        a3 = fmaf(wk[k], v[k + 3], a3);
    }
#pragma unroll
    for (int k = 5; k < 9; k++) {
        e0 = fmaf(wk[k], v[k + 0], e0);
        e1 = fmaf(wk[k], v[k + 1], e1);
        e2 = fmaf(wk[k], v[k + 2], e2);
        e3 = fmaf(wk[k], v[k + 3], e3);
    }
    d0 = fmaxf(a0 + e0, 0.f) + x0;
    d1 = fmaxf(a1 + e1, 0.f) + x1;
    d2 = fmaxf(a2 + e2, 0.f) + x2;
    d3 = fmaxf(a3 + e3, 0.f) + x3;
}

// In-place NHWC column scan, cp.async ring depth 16, pair-unrolled, per-element
// wait/commit; unroll-4 makes slot offsets compile-time.
__device__ __forceinline__ void scan_col_ring16(float* __restrict__ p, int stride,
                                                float* __restrict__ ring,
                                                const float wk[9], float b, int lane)
{
    float4 v0 = ld4(p);
    float d0 = v0.x, d1 = v0.y, d2 = v0.z, d3 = v0.w;
    *(float4*)p = relu4(d0, d1, d2, d3);

    float* my = ring + lane * 4;   // slot s at my + s*128
#pragma unroll
    for (int i = 0; i < 16; i++) {
        __pipeline_memcpy_async(my + i * 128, p + (1 + i) * stride, 16);
        __pipeline_commit();
    }
#pragma unroll 4
    for (int t = 1; t + 1 < 160; t += 2) {
        __pipeline_wait_prior(14);               // elements t, t+1 complete
        float* sl0 = my + ((t - 1) & 15) * 128;
        float* sl1 = my + (t & 15) * 128;
        float4 cx0 = *(float4*)sl0;
        float4 cx1 = *(float4*)sl1;
        if (t + 16 < 160) __pipeline_memcpy_async(sl0, p + (t + 16) * stride, 16);
        __pipeline_commit();
        if (t + 17 < 160) __pipeline_memcpy_async(sl1, p + (t + 17) * stride, 16);
        __pipeline_commit();
        scan_step(d0, d1, d2, d3, cx0.x, cx0.y, cx0.z, cx0.w, wk, b, lane);
        *(float4*)(p + t * stride) = relu4(d0, d1, d2, d3);
        scan_step(d0, d1, d2, d3, cx1.x, cx1.y, cx1.z, cx1.w, wk, b, lane);
        *(float4*)(p + (t + 1) * stride) = relu4(d0, d1, d2, d3);
    }
    // t = 159
    __pipeline_wait_prior(0);
    float4 cx = *(float4*)(my + ((159 - 1) & 15) * 128);
    scan_step(d0, d1, d2, d3, cx.x, cx.y, cx.z, cx.w, wk, b, lane);
    *(float4*)(p + 159 * stride) = relu4(d0, d1, d2, d3);
}

// Transpose kernel: x NCHW -> g_buf NHWC (raw copy, no math). One block per
// (n, h, 32-wide w tile). smem tile [32 w][132] (pad 4): both phases bank-
// conflict-free; LDG.128 (w-contiguous) and STG.128 (c-contiguous) coalesced.
__global__ void __launch_bounds__(128) k_tr(const float* __restrict__ x)
{
    __shared__ float sm[32 * 132];               // ~16.9 KB
    const int tid = threadIdx.x, lane = tid & 31, warp = tid >> 5;
    const int b = blockIdx.x;                    // n*(160*5) + h*5 + wb
    const int n = b / (Hh * 5);
    const int r = b % (Hh * 5);
    const int h = r / 5, w0 = (r % 5) * 32;

    // Read: thread owns channel c = tid, loads 32 w's as 8 float4.
    const float* xp = x + ((size_t)(n * Cc + tid) * Hh + h) * Ww + w0;
#pragma unroll
    for (int wq = 0; wq < 8; wq++) {
        float4 v = ld4(xp + wq * 4);
        sm[(wq * 4 + 0) * 132 + tid] = v.x;
        sm[(wq * 4 + 1) * 132 + tid] = v.y;
        sm[(wq * 4 + 2) * 132 + tid] = v.z;
        sm[(wq * 4 + 3) * 132 + tid] = v.w;
    }
    __syncthreads();

    // Write: warp k handles w = 4*i + k; lanes cover the 512B c-row.
    float* ob = g_buf + ((size_t)(n * Hh + h) * Ww + w0) * Cc + 4 * lane;
#pragma unroll
    for (int i = 0; i < 8; i++) {
        const int w = 4 * i + warp;
        float4 u = *(float4*)&sm[w * 132 + 4 * lane];
        *(float4*)(ob + (size_t)w * Cc) = u;
    }
}

// Pass 1 scan (down, H ascending) — in place on NHWC g_buf. One warp per block.
__global__ void __launch_bounds__(32) k_pass1s(const float* __restrict__ wgt,
                                               const float* __restrict__ bia)
{
    __shared__ float ring[16 * 128];             // 8 KB
    const int lane = threadIdx.x & 31;
    const int col = blockIdx.x;                  // n*W + w
    const int n = col / Ww, w = col % Ww;
    float wk[9];
#pragma unroll
    for (int k = 0; k < 9; k++) wk[k] = wgt[k];
    const float b = bia[0];
    const int base = n * HWC + w * Cc + lane * 4;                  // h = 0
    scan_col_ring16(g_buf + base, WC, ring, wk, b, lane);
}

// Pass 2 (up, H descending) — in place. One warp per block.
__global__ void __launch_bounds__(32) k_pass2(const float* __restrict__ wgt,
                                              const float* __restrict__ bia)
{
    __shared__ float ring[16 * 128];             // 8 KB
    const int lane = threadIdx.x & 31;
    const int col = blockIdx.x;                  // n*W + w
    const int n = col / Ww, w = col % Ww;
    float wk[9];
#pragma unroll
    for (int k = 0; k < 9; k++) wk[k] = wgt[k];
    const float b = bia[0];
    const int base = n * HWC + (Hh - 1) * WC + w * Cc + lane * 4;  // h = H-1
    scan_col_ring16(g_buf + base, -WC, ring, wk, b, lane);
}

// Pass 3 (left, W ascending) — in place. One warp per block.
__global__ void __launch_bounds__(32) k_pass3(const float* __restrict__ wgt,
                                              const float* __restrict__ bia)
{
    __shared__ float ring[16 * 128];
    const int lane = threadIdx.x & 31;
    const int col = blockIdx.x;                  // n*H + h
    const int n = col / Hh, h = col % Hh;
    float wk[9];
#pragma unroll
    for (int k = 0; k < 9; k++) wk[k] = wgt[k];
    const float b = bia[0];
    const int base = n * HWC + h * WC + lane * 4;                  // w = 0
    scan_col_ring16(g_buf + base, Cc, ring, wk, b, lane);
}

// Pass 4 (right, W descending): g_buf NHWC -> d_out NCHW, both spatial axes
// flipped (reference never un-flips). Depth-16 ring; warp-private 16-step
// XOR-swizzled stage; flush writes 8 full 64B lines per STG round.
__device__ __forceinline__ void p4_stage_write(float* stg, int row, int c0,
                                               float4 val)
{
    const int pc = c0 ^ (8 * ((row >> 2) & 3));
    *(float4*)(stg + row * 128 + pc) = val;
}

__global__ void __launch_bounds__(32) k_pass4(const float* __restrict__ wgt,
                                              const float* __restrict__ bia,
                                              float* __restrict__ out)
{
    __shared__ float ring[16 * 128];             // 8 KB
    __shared__ float stage[16 * 128];            // 8 KB (swizzled)
    const int lane = threadIdx.x & 31;
    const int col = blockIdx.x;                  // n*H + h
    const int n = col / Hh, h = col % Hh;
    float wk[9];
#pragma unroll
    for (int k = 0; k < 9; k++) wk[k] = wgt[k];
    const float b = bia[0];
    const int c0 = lane * 4;

    const float* inp = g_buf + n * HWC + h * WC + c0;  // + w*Cc
    float* stg = stage;
    const int tq = lane & 3, cq = lane >> 2;
    const int hrow = Hh - 1 - h;                 // flipped output h
    float* const obase = out + ((size_t)n * Cc * Hh + hrow) * Ww;

    // s = 0 <-> w = W-1
    float4 v0 = ld4(inp + (Ww - 1) * Cc);
    float d0 = v0.x, d1 = v0.y, d2 = v0.z, d3 = v0.w;
    p4_stage_write(stg, 0, c0, relu4(d0, d1, d2, d3));

    float* my = ring + lane * 4;
#pragma unroll
    for (int i = 0; i < 16; i++) {               // element s = 1+i
        __pipeline_memcpy_async(my + i * 128, inp + (Ww - 2 - i) * Cc, 16);
        __pipeline_commit();
    }

#define P4_FLUSH(S0)                                                        \
    do {                                                                    \
        __syncwarp();                                                       \
        _Pragma("unroll")                                                   \
        for (int cb = 0; cb < 16; cb++) {                                   \
            const int c = cb * 8 + cq;                                      \
            const int pcf = c ^ (8 * tq);                                   \
            float4 val = make_float4(stg[(4 * tq + 0) * 128 + pcf],         \
                                     stg[(4 * tq + 1) * 128 + pcf],         \
                                     stg[(4 * tq + 2) * 128 + pcf],         \
                                     stg[(4 * tq + 3) * 128 + pcf]);        \
            __stcs((float4*)(obase + (size_t)c * HW + (S0) + 4 * tq), val); \
        }                                                                   \
        __syncwarp();                                                       \
    } while (0)

#pragma unroll 4
    for (int s = 1; s + 1 < 160; s += 2) {       // s odd: only s can hit 15 mod 16
        __pipeline_wait_prior(14);
        float* sl0 = my + ((s - 1) & 15) * 128;
        float* sl1 = my + (s & 15) * 128;
        float4 cx0 = *(float4*)sl0;
        float4 cx1 = *(float4*)sl1;
        if (s + 16 < 160) __pipeline_memcpy_async(sl0, inp + (Ww - 1 - (s + 16)) * Cc, 16);
        __pipeline_commit();
        if (s + 17 < 160) __pipeline_memcpy_async(sl1, inp + (Ww - 1 - (s + 17)) * Cc, 16);
        __pipeline_commit();

        scan_step(d0, d1, d2, d3, cx0.x, cx0.y, cx0.z, cx0.w, wk, b, lane);
        p4_stage_write(stg, s & 15, c0, relu4(d0, d1, d2, d3));
        if ((s & 15) == 15) P4_FLUSH(s - 15);

        scan_step(d0, d1, d2, d3, cx1.x, cx1.y, cx1.z, cx1.w, wk, b, lane);
        p4_stage_write(stg, (s + 1) & 15, c0, relu4(d0, d1, d2, d3));
    }
    // s = 159
    __pipeline_wait_prior(0);
    {
        float4 cx = *(float4*)(my + ((159 - 1) & 15) * 128);
        scan_step(d0, d1, d2, d3, cx.x, cx.y, cx.z, cx.w, wk, b, lane);
        p4_stage_write(stg, 15, c0, relu4(d0, d1, d2, d3));
        P4_FLUSH(144);
    }
#undef P4_FLUSH
}

extern "C" void kernel_launch(void* const* d_in, const int* in_sizes, int n_in,
                              void* d_out, int out_size)
{
    (void)in_sizes; (void)n_in; (void)out_size;
    const float* x  = (const float*)d_in[0];
    const float* wd = (const float*)d_in[1];
    const float* bd = (const float*)d_in[2];
    const float* wu = (const float*)d_in[3];
    const float* bu = (const float*)d_in[4];
    const float* wl = (const float*)d_in[5];
    const float* bl = (const float*)d_in[6];
    const float* wr = (const float*)d_in[7];
    const float* br = (const float*)d_in[8];
    float* out = (float*)d_out;

    k_tr<<<Nn * Hh * 5, 128>>>(x);
    k_pass1s<<<1280, 32>>>(wd, bd);
    k_pass2<<<1280, 32>>>(wu, bu);
    k_pass3<<<1280, 32>>>(wl, bl);
    k_pass4<<<1280, 32>>>(wr, br, out);
}

// round 17
// speedup vs baseline: 1.2098x; 1.2098x over previous
#include <cuda_runtime.h>
#include <cuda_pipeline.h>

#define FULLMASK 0xffffffffu

constexpr int Nn = 8;
constexpr int Cc = 128;
constexpr int Hh = 160;
constexpr int Ww = 160;
constexpr int HW  = Hh * Ww;
constexpr int WC  = Ww * Cc;
constexpr int HWC = Hh * WC;             // per-image NHWC stride
constexpr int TOT = Nn * HWC;

// Single in-place NHWC scratch buffer.
__device__ float g_buf[TOT];

__device__ __forceinline__ float4 ld4(const float* p)  { return *(const float4*)p; }

__device__ __forceinline__ float4 relu4(float a, float b, float c, float d) {
    return make_float4(fmaxf(a, 0.f), fmaxf(b, 0.f), fmaxf(c, 0.f), fmaxf(d, 0.f));
}

// One scan step: carry d0..d3 (pre-relu state, 4 consecutive channels/lane),
// 9-tap conv along C via lane shuffles, zero-padded at C boundaries.
// d_new = relu(conv(d) + b) + x. Split accumulators shorten the FMA chain.
__device__ __forceinline__ void scan_step(float& d0, float& d1, float& d2, float& d3,
                                          float x0, float x1, float x2, float x3,
                                          const float wk[9], float b, int lane)
{
    float v[12];
    v[4] = d0; v[5] = d1; v[6] = d2; v[7] = d3;
    v[0]  = __shfl_up_sync(FULLMASK, d0, 1);
    v[1]  = __shfl_up_sync(FULLMASK, d1, 1);
    v[2]  = __shfl_up_sync(FULLMASK, d2, 1);
    v[3]  = __shfl_up_sync(FULLMASK, d3, 1);
    v[8]  = __shfl_down_sync(FULLMASK, d0, 1);
    v[9]  = __shfl_down_sync(FULLMASK, d1, 1);
    v[10] = __shfl_down_sync(FULLMASK, d2, 1);
    v[11] = __shfl_down_sync(FULLMASK, d3, 1);
    if (lane == 0)  { v[0] = 0.f; v[1] = 0.f; v[2]  = 0.f; v[3]  = 0.f; }
    if (lane == 31) { v[8] = 0.f; v[9] = 0.f; v[10] = 0.f; v[11] = 0.f; }
    float a0 = b, a1 = b, a2 = b, a3 = b;
    float e0 = 0.f, e1 = 0.f, e2 = 0.f, e3 = 0.f;
#pragma unroll
    for (int k = 0; k < 5; k++) {
        a0 = fmaf(wk[k], v[k + 0], a0);
        a1 = fmaf(wk[k], v[k + 1], a1);
        a2 = fmaf(wk[k], v[k + 2], a2);
        a3 = fmaf(wk[k], v[k + 3], a3);
    }
#pragma unroll
    for (int k = 5; k < 9; k++) {
        e0 = fmaf(wk[k], v[k + 0], e0);
        e1 = fmaf(wk[k], v[k + 1], e1);
        e2 = fmaf(wk[k], v[k + 2], e2);
        e3 = fmaf(wk[k], v[k + 3], e3);
    }
    d0 = fmaxf(a0 + e0, 0.f) + x0;
    d1 = fmaxf(a1 + e1, 0.f) + x1;
    d2 = fmaxf(a2 + e2, 0.f) + x2;
    d3 = fmaxf(a3 + e3, 0.f) + x3;
}

// In-place NHWC column scan, cp.async ring depth 16, pair-unrolled, per-element
// wait/commit; unroll-4 makes slot offsets compile-time. Fully drains its
// pipeline groups before returning.
__device__ __forceinline__ void scan_col_ring16(float* __restrict__ p, int stride,
                                                float* __restrict__ ring,
                                                const float wk[9], float b, int lane)
{
    float4 v0 = ld4(p);
    float d0 = v0.x, d1 = v0.y, d2 = v0.z, d3 = v0.w;
    *(float4*)p = relu4(d0, d1, d2, d3);

    float* my = ring + lane * 4;   // slot s at my + s*128
#pragma unroll
    for (int i = 0; i < 16; i++) {
        __pipeline_memcpy_async(my + i * 128, p + (1 + i) * stride, 16);
        __pipeline_commit();
    }
#pragma unroll 4
    for (int t = 1; t + 1 < 160; t += 2) {
        __pipeline_wait_prior(14);               // elements t, t+1 complete
        float* sl0 = my + ((t - 1) & 15) * 128;
        float* sl1 = my + (t & 15) * 128;
        float4 cx0 = *(float4*)sl0;
        float4 cx1 = *(float4*)sl1;
        if (t + 16 < 160) __pipeline_memcpy_async(sl0, p + (t + 16) * stride, 16);
        __pipeline_commit();
        if (t + 17 < 160) __pipeline_memcpy_async(sl1, p + (t + 17) * stride, 16);
        __pipeline_commit();
        scan_step(d0, d1, d2, d3, cx0.x, cx0.y, cx0.z, cx0.w, wk, b, lane);
        *(float4*)(p + t * stride) = relu4(d0, d1, d2, d3);
        scan_step(d0, d1, d2, d3, cx1.x, cx1.y, cx1.z, cx1.w, wk, b, lane);
        *(float4*)(p + (t + 1) * stride) = relu4(d0, d1, d2, d3);
    }
    // t = 159
    __pipeline_wait_prior(0);
    float4 cx = *(float4*)(my + ((159 - 1) & 15) * 128);
    scan_step(d0, d1, d2, d3, cx.x, cx.y, cx.z, cx.w, wk, b, lane);
    *(float4*)(p + 159 * stride) = relu4(d0, d1, d2, d3);
}

// Fused passes 1+2. Phase A (down, H ascending): x NCHW -> g_buf NHWC via
// cp.async staged transpose (R12 k_pass1, unchanged). Phase B (up, H
// descending): each warp re-scans its own column in place — the 80 KB column
// is freshly written => L2-hot. Phase-B rings alias the staging buffer.
__global__ void __launch_bounds__(128) k_p12(const float* __restrict__ x,
                                             const float* __restrict__ wgt_d,
                                             const float* __restrict__ bia_d,
                                             const float* __restrict__ wgt_u,
                                             const float* __restrict__ bia_u)
{
    constexpr int SLOTS = 18, DEPTH = 16, SLOTW = 128 * 4 + 16 * 4;  // 576 words
    __shared__ float r1[SLOTS * SLOTW];          // ~41.5 KB (phase B: 4x8KB rings)
    const int tid = threadIdx.x, lane = tid & 31, warp = tid >> 5;
    const int col0 = blockIdx.x * 4;             // 4 consecutive w, same n
    const int n = col0 / Ww, w0 = col0 % Ww;
    float wk[9];
#pragma unroll
    for (int k = 0; k < 9; k++) wk[k] = wgt_d[k];
    const float b = bia_d[0];

    const float* xb = x + ((size_t)n * Cc + tid) * HW + w0;   // + h*Ww
    float* ob = g_buf + (size_t)n * HWC + (size_t)(w0 + warp) * Cc + lane * 4;

    const int dstw = tid * 4 + (tid >> 3) * 4;   // 16B chunk, 16B gap per 8 rows
#pragma unroll
    for (int i = 0; i < DEPTH; i++) {
        __pipeline_memcpy_async(r1 + i * SLOTW + dstw, xb + i * Ww, 16);
        __pipeline_commit();
    }

    // transposed read offsets: channels 4*lane..+3 of column `warp`
    const int cA = 4 * lane;
    const int rx0 = (cA + 0) * 4 + ((cA + 0) >> 3) * 4 + warp;
    const int rx1 = (cA + 1) * 4 + ((cA + 1) >> 3) * 4 + warp;
    const int rx2 = (cA + 2) * 4 + ((cA + 2) >> 3) * 4 + warp;
    const int rx3 = (cA + 3) * 4 + ((cA + 3) >> 3) * 4 + warp;

    float d0 = 0.f, d1 = 0.f, d2 = 0.f, d3 = 0.f;
    int sl_r = 0, sl_w = DEPTH;
    for (int h = 0; h < 160; h += 2) {
        __pipeline_wait_prior(DEPTH - 2);        // this thread's h, h+1 landed
        __syncthreads();                         // all threads' copies visible
        int sr1 = sl_r + 1; if (sr1 == SLOTS) sr1 = 0;
        const float* b0 = r1 + sl_r * SLOTW;
        const float* b1 = r1 + sr1 * SLOTW;
        float c00 = b0[rx0], c01 = b0[rx1], c02 = b0[rx2], c03 = b0[rx3];
        float c10 = b1[rx0], c11 = b1[rx1], c12 = b1[rx2], c13 = b1[rx3];
        int sw1 = sl_w + 1; if (sw1 == SLOTS) sw1 = 0;
        if (h + DEPTH < Hh)
            __pipeline_memcpy_async(r1 + sl_w * SLOTW + dstw, xb + (h + DEPTH) * Ww, 16);
        __pipeline_commit();
        if (h + DEPTH + 1 < Hh)
            __pipeline_memcpy_async(r1 + sw1 * SLOTW + dstw, xb + (h + DEPTH + 1) * Ww, 16);
        __pipeline_commit();

        if (h == 0) { d0 = c00; d1 = c01; d2 = c02; d3 = c03; }
        else scan_step(d0, d1, d2, d3, c00, c01, c02, c03, wk, b, lane);
        *(float4*)(ob + h * WC) = relu4(d0, d1, d2, d3);
        scan_step(d0, d1, d2, d3, c10, c11, c12, c13, wk, b, lane);
        *(float4*)(ob + (h + 1) * WC) = relu4(d0, d1, d2, d3);

        sl_r += 2; if (sl_r >= SLOTS) sl_r -= SLOTS;
        sl_w += 2; if (sl_w >= SLOTS) sl_w -= SLOTS;
    }

    // ---- Phase B: pass 2 (up) on this block's own 4 columns ----
    __pipeline_wait_prior(0);                    // drain phase-A groups
    __syncthreads();                             // r1 free for reuse as rings
    float wku[9];
#pragma unroll
    for (int k = 0; k < 9; k++) wku[k] = wgt_u[k];
    const float bu = bia_u[0];
    float* ring = r1 + warp * (16 * 128);        // 8 KB per warp (32 KB < 41.5 KB)
    const int base = n * HWC + (Hh - 1) * WC + (w0 + warp) * Cc + lane * 4;
    scan_col_ring16(g_buf + base, -WC, ring, wku, bu, lane);
}

// Fused passes 3+4 per (n,h) row. Phase A (left, W ascending): in-place ring
// scan (R12 k_pass3). Phase B (right, W descending): R12 k_pass4 — its reads
// hit the freshly written row in L2. One shared 8 KB ring, 8 KB out-stage.
__device__ __forceinline__ void p4_stage_write(float* stg, int row, int c0,
                                               float4 val)
{
    const int pc = c0 ^ (8 * ((row >> 2) & 3));
    *(float4*)(stg + row * 128 + pc) = val;
}

__global__ void __launch_bounds__(32) k_p34(const float* __restrict__ wgt_l,
                                            const float* __restrict__ bia_l,
                                            const float* __restrict__ wgt_r,
                                            const float* __restrict__ bia_r,
                                            float* __restrict__ out)
{
    __shared__ float ring[16 * 128];             // 8 KB (both phases)
    __shared__ float stage[16 * 128];            // 8 KB (swizzled, phase B)
    const int lane = threadIdx.x & 31;
    const int col = blockIdx.x;                  // n*H + h
    const int n = col / Hh, h = col % Hh;
    const int c0 = lane * 4;

    // ---- Phase A: pass 3 (left) ----
    {
        float wk[9];
#pragma unroll
        for (int k = 0; k < 9; k++) wk[k] = wgt_l[k];
        const float b = bia_l[0];
        const int base = n * HWC + h * WC + c0;  // w = 0
        scan_col_ring16(g_buf + base, Cc, ring, wk, b, lane);
    }
    __syncwarp();

    // ---- Phase B: pass 4 (right) -> out NCHW, both spatial axes flipped ----
    float wk[9];
#pragma unroll
    for (int k = 0; k < 9; k++) wk[k] = wgt_r[k];
    const float b = bia_r[0];

    const float* inp = g_buf + n * HWC + h * WC + c0;  // + w*Cc
    float* stg = stage;
    const int tq = lane & 3, cq = lane >> 2;
    const int hrow = Hh - 1 - h;                 // flipped output h
    float* const obase = out + ((size_t)n * Cc * Hh + hrow) * Ww;

    // s = 0 <-> w = W-1
    float4 v0 = ld4(inp + (Ww - 1) * Cc);
    float d0 = v0.x, d1 = v0.y, d2 = v0.z, d3 = v0.w;
    p4_stage_write(stg, 0, c0, relu4(d0, d1, d2, d3));

    float* my = ring + lane * 4;
#pragma unroll
    for (int i = 0; i < 16; i++) {               // element s = 1+i
        __pipeline_memcpy_async(my + i * 128, inp + (Ww - 2 - i) * Cc, 16);
        __pipeline_commit();
    }

#define P4_FLUSH(S0)                                                        \
    do {                                                                    \
        __syncwarp();                                                       \
        _Pragma("unroll")                                                   \
        for (int cb = 0; cb < 16; cb++) {                                   \
            const int c = cb * 8 + cq;                                      \
            const int pcf = c ^ (8 * tq);                                   \
            float4 val = make_float4(stg[(4 * tq + 0) * 128 + pcf],         \
                                     stg[(4 * tq + 1) * 128 + pcf],         \
                                     stg[(4 * tq + 2) * 128 + pcf],         \
                                     stg[(4 * tq + 3) * 128 + pcf]);        \
            __stcs((float4*)(obase + (size_t)c * HW + (S0) + 4 * tq), val); \
        }                                                                   \
        __syncwarp();                                                       \
    } while (0)

#pragma unroll 4
    for (int s = 1; s + 1 < 160; s += 2) {       // s odd: only s can hit 15 mod 16
        __pipeline_wait_prior(14);
        float* sl0 = my + ((s - 1) & 15) * 128;
        float* sl1 = my + (s & 15) * 128;
        float4 cx0 = *(float4*)sl0;
        float4 cx1 = *(float4*)sl1;
        if (s + 16 < 160) __pipeline_memcpy_async(sl0, inp + (Ww - 1 - (s + 16)) * Cc, 16);
        __pipeline_commit();
        if (s + 17 < 160) __pipeline_memcpy_async(sl1, inp + (Ww - 1 - (s + 17)) * Cc, 16);
        __pipeline_commit();

        scan_step(d0, d1, d2, d3, cx0.x, cx0.y, cx0.z, cx0.w, wk, b, lane);
        p4_stage_write(stg, s & 15, c0, relu4(d0, d1, d2, d3));
        if ((s & 15) == 15) P4_FLUSH(s - 15);

        scan_step(d0, d1, d2, d3, cx1.x, cx1.y, cx1.z, cx1.w, wk, b, lane);
        p4_stage_write(stg, (s + 1) & 15, c0, relu4(d0, d1, d2, d3));
    }
    // s = 159
    __pipeline_wait_prior(0);
    {
        float4 cx = *(float4*)(my + ((159 - 1) & 15) * 128);
        scan_step(d0, d1, d2, d3, cx.x, cx.y, cx.z, cx.w, wk, b, lane);
        p4_stage_write(stg, 15, c0, relu4(d0, d1, d2, d3));
        P4_FLUSH(144);
    }
#undef P4_FLUSH
}

extern "C" void kernel_launch(void* const* d_in, const int* in_sizes, int n_in,
                              void* d_out, int out_size)
{
    (void)in_sizes; (void)n_in; (void)out_size;
    const float* x  = (const float*)d_in[0];
    const float* wd = (const float*)d_in[1];
    const float* bd = (const float*)d_in[2];
    const float* wu = (const float*)d_in[3];
    const float* bu = (const float*)d_in[4];
    const float* wl = (const float*)d_in[5];
    const float* bl = (const float*)d_in[6];
    const float* wr = (const float*)d_in[7];
    const float* br = (const float*)d_in[8];
    float* out = (float*)d_out;

    k_p12<<<320, 128>>>(x, wd, bd, wu, bu);
    k_p34<<<1280, 32>>>(wl, bl, wr, br, out);
}